// round 9
// baseline (speedup 1.0000x reference)
#include <cuda_runtime.h>
#include <cuda_fp16.h>

// Problem constants (fixed by the dataset's reference_code)
#define HW_DIM     512
#define NB         6
#define NLOOPS     4
#define NDET       4096
#define NSAMP      128
#define NBATCH     4
#define NPTS       (NDET * NSAMP)          // 524288
#define PIX        (512 * 512)             // per-channel elements
#define B_STRIDE   (2 * NB * PIX)          // per-batch elements (12 channels)
#define TILE       2048                    // pixels per repack block
#define ILP        2                       // points per refine thread

// Pair-packed refinement, 8 B per (pixel, bucket-pair):
//   g_pairs[parity][b][j][pix] = (x_ka, y_ka, x_kb, y_kb) as 4x fp16
//   parity 0 (E): pairs (0,1),(2,3),(4,5)   ka=2j,   kb=2j+1
//   parity 1 (O): pairs (1,2),(3,4),(5,0)   ka=2j+1, kb=(2j+2)%6
// For taps (k0, k0+1 mod 6): parity = k0&1, j = k0>>1, first slot = k0. 50 MB.
__device__ uint2 g_pairs[2 * NBATCH * 3 * PIX];

// Pack two floats to one fp16x2 payload as a raw 32-bit word.
static __device__ __forceinline__ unsigned pack_h2(float a, float b)
{
    __half2 h = __floats2half2_rn(a, b);
    return *reinterpret_cast<unsigned*>(&h);
}

// ---------------------------------------------------------------------------
// Repack: minimum traffic (50 MB read + 50 MB write), smem-staged.
// Block = (batch, 2048-pixel tile). Phase 1: stage 6 buckets as h2 words.
// Phase 2: emit 6 pair-volumes with coalesced uint4 stores.
// ---------------------------------------------------------------------------
__global__ void __launch_bounds__(256)
repack_kernel(const float* __restrict__ refinement)
{
    __shared__ unsigned sm[NB][TILE];       // 6*2048*4 = 48 KB

    const int b    = blockIdx.x >> 7;       // PIX/TILE = 128 tiles per batch
    const int base = (blockIdx.x & 127) * TILE;
    const int tid  = threadIdx.x;

    // Phase 1: stage (x,y) of each bucket as packed h2 words
    #pragma unroll
    for (int k = 0; k < NB; ++k) {
        const float4* cx = reinterpret_cast<const float4*>(
            refinement + (long)b * B_STRIDE + (long)(2 * k)     * PIX + base);
        const float4* cy = reinterpret_cast<const float4*>(
            refinement + (long)b * B_STRIDE + (long)(2 * k + 1) * PIX + base);
        #pragma unroll
        for (int i = tid; i < TILE / 4; i += 256) {
            const float4 xv = cx[i];
            const float4 yv = cy[i];
            sm[k][4 * i + 0] = pack_h2(xv.x, yv.x);
            sm[k][4 * i + 1] = pack_h2(xv.y, yv.y);
            sm[k][4 * i + 2] = pack_h2(xv.z, yv.z);
            sm[k][4 * i + 3] = pack_h2(xv.w, yv.w);
        }
    }
    __syncthreads();

    // Phase 2: emit pair volumes (2 pixels per uint4 store)
    #pragma unroll
    for (int v = 0; v < 6; ++v) {
        const int parity = v / 3;
        const int j      = v - parity * 3;
        const int ka     = parity ? (2 * j + 1) : (2 * j);
        const int kb     = parity ? ((2 * j + 2) % NB) : (2 * j + 1);

        uint4* dst = reinterpret_cast<uint4*>(
            g_pairs + ((long)(parity * NBATCH + b) * 3 + j) * PIX + base);
        #pragma unroll
        for (int i = tid; i < TILE / 2; i += 256) {
            const int p = 2 * i;
            uint4 o;
            o.x = sm[ka][p    ];
            o.y = sm[kb][p    ];
            o.z = sm[ka][p + 1];
            o.w = sm[kb][p + 1];
            dst[i] = o;
        }
    }
}

// ---------------------------------------------------------------------------
// Refine: ONE 8B gather per iteration, ILP=2 independent points per thread.
// Exact work-skipping: fixed-point and 2-cycle exits.
// ---------------------------------------------------------------------------
__global__ void __launch_bounds__(256)
refine_kernel(const float*  __restrict__ det_in,     // [NDET, NSAMP, 2]
              const float*  __restrict__ sampling,   // [NSAMP]
              const int*    __restrict__ bvec,       // [NDET]
              float*        __restrict__ out)        // [NDET, NSAMP, 2]
{
    const int t0 = blockIdx.x * (256 * ILP) + threadIdx.x;

    float x[ILP], y[ILP], px[ILP], py[ILP], w0[ILP], w1[ILP];
    const uint2* ptr[ILP];
    int  prev1[ILP], prev2[ILP];
    bool done[ILP];

    #pragma unroll
    for (int i = 0; i < ILP; ++i) {
        const int t = t0 + i * 256;
        const int s = t & (NSAMP - 1);
        const int d = t >> 7;

        // Per-sample bucket setup — reference arithmetic exactly.
        const float base = sampling[s] * (float)NB;
        const float bif  = floorf(base);
        const int   bint = (int)bif;

        const float d0 = fabsf(bif - base);
        w0[i] = (d0 > 1.0f) ? 0.0f : (1.0f - d0);
        const float d1 = fabsf((bif + 1.0f) - base);
        w1[i] = (d1 > 1.0f) ? 0.0f : (1.0f - d1);

        const int k0     = bint % NB;
        const int parity = k0 & 1;
        const int j      = k0 >> 1;
        ptr[i] = g_pairs + ((long)(parity * NBATCH + bvec[d]) * 3 + j) * PIX;

        const float2 det = reinterpret_cast<const float2*>(det_in)[t];
        x[i] = det.x;  y[i] = det.y;
        px[i] = det.x; py[i] = det.y;
        prev1[i] = -1; prev2[i] = -1; done[i] = false;
    }

    #pragma unroll
    for (int l = 0; l < NLOOPS; ++l) {
        float xr[ILP], yr[ILP];
        int   pix[ILP];
        bool  act[ILP];
        uint2 v[ILP];

        #pragma unroll
        for (int i = 0; i < ILP; ++i) {
            act[i] = !done[i];
            if (act[i]) {
                float xv = rintf(x[i]);      // round-half-even == jnp.round
                float yv = rintf(y[i]);
                xv = fminf(fmaxf(xv, 0.0f), (float)(HW_DIM - 1));
                yv = fminf(fmaxf(yv, 0.0f), (float)(HW_DIM - 1));
                xr[i] = xv;  yr[i] = yv;
                pix[i] = (int)yv * HW_DIM + (int)xv;

                if (pix[i] == prev1[i]) {            // fixed point
                    done[i] = true; act[i] = false;
                } else if (pix[i] == prev2[i]) {     // 2-cycle
                    if ((NLOOPS - l) & 1) { x[i] = px[i]; y[i] = py[i]; }
                    done[i] = true; act[i] = false;
                } else {
                    prev2[i] = prev1[i];  prev1[i] = pix[i];
                    px[i] = x[i];  py[i] = y[i];
                }
            }
        }

        #pragma unroll
        for (int i = 0; i < ILP; ++i)
            if (act[i]) v[i] = __ldg(ptr[i] + pix[i]);

        #pragma unroll
        for (int i = 0; i < ILP; ++i) {
            if (act[i]) {
                const float2 g0 = __half22float2(*reinterpret_cast<__half2*>(&v[i].x));
                const float2 g1 = __half22float2(*reinterpret_cast<__half2*>(&v[i].y));
                x[i] = xr[i] + (w0[i] * g0.x + w1[i] * g1.x);
                y[i] = yr[i] + (w0[i] * g0.y + w1[i] * g1.y);
            }
        }
    }

    #pragma unroll
    for (int i = 0; i < ILP; ++i) {
        const int t = t0 + i * 256;
        reinterpret_cast<float2*>(out)[t] = make_float2(x[i], y[i]);
    }
}

extern "C" void kernel_launch(void* const* d_in, const int* in_sizes, int n_in,
                              void* d_out, int out_size)
{
    // Identify inputs by element count:
    //   det_indices : 1048576 f32, refinement : 12582912 f32,
    //   sampling : 128 f32, b : 4096 i32
    const float* det_in     = nullptr;
    const float* refinement = nullptr;
    const float* sampling   = nullptr;
    const int*   bvec       = nullptr;

    for (int i = 0; i < n_in; ++i) {
        switch (in_sizes[i]) {
            case 1048576:  det_in     = (const float*)d_in[i]; break;
            case 12582912: refinement = (const float*)d_in[i]; break;
            case 128:      sampling   = (const float*)d_in[i]; break;
            case 4096:     bvec       = (const int*)d_in[i];   break;
            default: break;
        }
    }

    repack_kernel<<<NBATCH * (PIX / TILE), 256>>>(refinement);   // 512 blocks
    refine_kernel<<<NPTS / (256 * ILP), 256>>>(det_in, sampling, bvec,
                                               (float*)d_out);   // 1024 blocks
}

// round 10
// speedup vs baseline: 1.1106x; 1.1106x over previous
#include <cuda_runtime.h>
#include <cuda_fp16.h>

// Problem constants (fixed by the dataset's reference_code)
#define HW_DIM     512
#define NB         6
#define NLOOPS     4
#define NDET       4096
#define NSAMP      128
#define NBATCH     4
#define NPTS       (NDET * NSAMP)          // 524288
#define PIX        (512 * 512)             // per-channel elements
#define B_STRIDE   (2 * NB * PIX)          // per-batch elements (12 channels)
#define ILP        2                       // points per refine thread

// Packed refinement: [BATCH][NB][H][W] of half2(x,y) = 25.2 MB.
__device__ __half2 g_packed[NBATCH * NB * PIX];

// ---------------------------------------------------------------------------
// Kernel 1: repack f32 channel pairs -> half2 (75 MB total traffic).
// Proven in R7 at 8.9 us. Each thread: 8 pixels.
// ---------------------------------------------------------------------------
__global__ void __launch_bounds__(256)
repack_kernel(const float* __restrict__ refinement)
{
    const int t = blockIdx.x * blockDim.x + threadIdx.x;
    const int oct   = t % (PIX / 8);
    const int slice = t / (PIX / 8);        // b*NB + k
    const int p     = oct * 8;

    const int b = slice / NB;
    const int k = slice - b * NB;

    const float* ch0 = refinement + (long)b * B_STRIDE + (long)(2 * k)     * PIX;
    const float* ch1 = refinement + (long)b * B_STRIDE + (long)(2 * k + 1) * PIX;

    const float4 x0 = *reinterpret_cast<const float4*>(ch0 + p);
    const float4 x1 = *reinterpret_cast<const float4*>(ch0 + p + 4);
    const float4 y0 = *reinterpret_cast<const float4*>(ch1 + p);
    const float4 y1 = *reinterpret_cast<const float4*>(ch1 + p + 4);

    __half2 h[8];
    h[0] = __floats2half2_rn(x0.x, y0.x);
    h[1] = __floats2half2_rn(x0.y, y0.y);
    h[2] = __floats2half2_rn(x0.z, y0.z);
    h[3] = __floats2half2_rn(x0.w, y0.w);
    h[4] = __floats2half2_rn(x1.x, y1.x);
    h[5] = __floats2half2_rn(x1.y, y1.y);
    h[6] = __floats2half2_rn(x1.z, y1.z);
    h[7] = __floats2half2_rn(x1.w, y1.w);

    uint4* dst = reinterpret_cast<uint4*>(&g_packed[(long)slice * PIX + p]);
    dst[0] = *reinterpret_cast<const uint4*>(&h[0]);
    dst[1] = *reinterpret_cast<const uint4*>(&h[4]);
}

// ---------------------------------------------------------------------------
// Kernel 2: refine, 2x 4B gathers per iteration, ILP=2 points per thread.
// Exact work-skipping: fixed-point and 2-cycle exits.
// ---------------------------------------------------------------------------
__global__ void __launch_bounds__(256)
refine_kernel(const float*  __restrict__ det_in,     // [NDET, NSAMP, 2]
              const float*  __restrict__ sampling,   // [NSAMP]
              const int*    __restrict__ bvec,       // [NDET]
              float*        __restrict__ out)        // [NDET, NSAMP, 2]
{
    const int t0 = blockIdx.x * (256 * ILP) + threadIdx.x;

    float x[ILP], y[ILP], px[ILP], py[ILP], w0[ILP], w1[ILP];
    int  off0[ILP], off1[ILP];               // element offsets into g_packed
    int  prev1[ILP], prev2[ILP];
    bool done[ILP];

    #pragma unroll
    for (int i = 0; i < ILP; ++i) {
        const int t = t0 + i * 256;
        const int s = t & (NSAMP - 1);
        const int d = t >> 7;

        // Per-sample bucket setup — reference arithmetic exactly.
        const float base = sampling[s] * (float)NB;
        const float bif  = floorf(base);
        const int   bint = (int)bif;

        const float d0 = fabsf(bif - base);
        w0[i] = (d0 > 1.0f) ? 0.0f : (1.0f - d0);
        const float d1 = fabsf((bif + 1.0f) - base);
        w1[i] = (d1 > 1.0f) ? 0.0f : (1.0f - d1);

        const int k0 = bint % NB;
        const int k1 = (bint + 1) % NB;
        const int bb = bvec[d] * NB;
        off0[i] = (bb + k0) * PIX;            // max 6.3M, fits int
        off1[i] = (bb + k1) * PIX;

        const float2 det = reinterpret_cast<const float2*>(det_in)[t];
        x[i] = det.x;  y[i] = det.y;
        px[i] = det.x; py[i] = det.y;
        prev1[i] = -1; prev2[i] = -1; done[i] = false;
    }

    #pragma unroll
    for (int l = 0; l < NLOOPS; ++l) {
        float  xr[ILP], yr[ILP];
        int    pix[ILP];
        bool   act[ILP];
        __half2 v0[ILP], v1[ILP];

        #pragma unroll
        for (int i = 0; i < ILP; ++i) {
            act[i] = !done[i];
            if (act[i]) {
                float xv = rintf(x[i]);       // round-half-even == jnp.round
                float yv = rintf(y[i]);
                xv = fminf(fmaxf(xv, 0.0f), (float)(HW_DIM - 1));
                yv = fminf(fmaxf(yv, 0.0f), (float)(HW_DIM - 1));
                xr[i] = xv;  yr[i] = yv;
                pix[i] = (int)yv * HW_DIM + (int)xv;

                if (pix[i] == prev1[i]) {             // fixed point
                    done[i] = true; act[i] = false;
                } else if (pix[i] == prev2[i]) {      // 2-cycle
                    if ((NLOOPS - l) & 1) { x[i] = px[i]; y[i] = py[i]; }
                    done[i] = true; act[i] = false;
                } else {
                    prev2[i] = prev1[i];  prev1[i] = pix[i];
                    px[i] = x[i];  py[i] = y[i];
                }
            }
        }

        // Issue all gathers together (up to 4 independent 4B loads in flight)
        #pragma unroll
        for (int i = 0; i < ILP; ++i) {
            if (act[i]) {
                v0[i] = __ldg(g_packed + off0[i] + pix[i]);
                v1[i] = __ldg(g_packed + off1[i] + pix[i]);
            }
        }

        #pragma unroll
        for (int i = 0; i < ILP; ++i) {
            if (act[i]) {
                const float2 g0 = __half22float2(v0[i]);
                const float2 g1 = __half22float2(v1[i]);
                x[i] = xr[i] + (w0[i] * g0.x + w1[i] * g1.x);
                y[i] = yr[i] + (w0[i] * g0.y + w1[i] * g1.y);
            }
        }
    }

    #pragma unroll
    for (int i = 0; i < ILP; ++i) {
        const int t = t0 + i * 256;
        reinterpret_cast<float2*>(out)[t] = make_float2(x[i], y[i]);
    }
}

extern "C" void kernel_launch(void* const* d_in, const int* in_sizes, int n_in,
                              void* d_out, int out_size)
{
    // Identify inputs by element count:
    //   det_indices : 1048576 f32, refinement : 12582912 f32,
    //   sampling : 128 f32, b : 4096 i32
    const float* det_in     = nullptr;
    const float* refinement = nullptr;
    const float* sampling   = nullptr;
    const int*   bvec       = nullptr;

    for (int i = 0; i < n_in; ++i) {
        switch (in_sizes[i]) {
            case 1048576:  det_in     = (const float*)d_in[i]; break;
            case 12582912: refinement = (const float*)d_in[i]; break;
            case 128:      sampling   = (const float*)d_in[i]; break;
            case 4096:     bvec       = (const int*)d_in[i];   break;
            default: break;
        }
    }

    {
        const int total = NBATCH * NB * (PIX / 8);     // 786432 threads
        repack_kernel<<<total / 256, 256>>>(refinement);
    }
    refine_kernel<<<NPTS / (256 * ILP), 256>>>(det_in, sampling, bvec,
                                               (float*)d_out);
}